// round 6
// baseline (speedup 1.0000x reference)
#include <cuda_runtime.h>
#include <cuda_bf16.h>
#include <math.h>

// ---------------------------------------------------------------------------
// GraphSAGE fraud detector, fp32 (R6): R2 design + half-warp paired gather
// (2 edges per warp LDG) + fused final colsum reduction.
// ---------------------------------------------------------------------------

#define MAXN 100000
#define MAXE 1600000
#define F 64

__device__ int   g_deg[MAXN];
__device__ int   g_rowstart[MAXN];
__device__ int   g_cursor[MAXN];
__device__ int   g_srcs[MAXE];
__device__ float g_aggr[(size_t)MAXN * F];
__device__ float g_bufA[(size_t)MAXN * F];
__device__ float g_bufB[(size_t)MAXN * F];
__device__ float g_colsum[F];
__device__ int   g_bsum[256];
__device__ int   g_boff[256];

// ---------------------------------------------------------------------------
__global__ void init_kernel(int nNodes) {
    int i = blockIdx.x * blockDim.x + threadIdx.x;
    if (i < nNodes) g_deg[i] = 0;
    if (i < F) g_colsum[i] = 0.f;
}

__global__ void hist_kernel(const int* __restrict__ dst, int E) {
    int e = blockIdx.x * blockDim.x + threadIdx.x;
    if (e < E) atomicAdd(&g_deg[dst[e]], 1);
}

// --- 3-phase parallel exclusive scan over degrees (2 nodes / thread) -------
__global__ void scan_pass1(int nNodes) {
    int t = threadIdx.x, b = blockIdx.x;
    int base = (b * 256 + t) * 2;
    int s = 0;
    if (base < nNodes) s += g_deg[base];
    if (base + 1 < nNodes) s += g_deg[base + 1];
    __shared__ int sh[256];
    sh[t] = s;
    __syncthreads();
    for (int o = 128; o > 0; o >>= 1) {
        if (t < o) sh[t] += sh[t + o];
        __syncthreads();
    }
    if (t == 0) g_bsum[b] = sh[0];
}

__global__ void scan_pass2() {
    __shared__ int sh[256];
    int t = threadIdx.x;
    int v = g_bsum[t];
    sh[t] = v;
    __syncthreads();
    for (int o = 1; o < 256; o <<= 1) {
        int u = (t >= o) ? sh[t - o] : 0;
        __syncthreads();
        sh[t] += u;
        __syncthreads();
    }
    g_boff[t] = sh[t] - v;
}

__global__ void scan_pass3(int nNodes) {
    int t = threadIdx.x, b = blockIdx.x;
    int base = (b * 256 + t) * 2;
    int d0 = (base < nNodes) ? g_deg[base] : 0;
    int d1 = (base + 1 < nNodes) ? g_deg[base + 1] : 0;
    int s = d0 + d1;
    __shared__ int sh[256];
    sh[t] = s;
    __syncthreads();
    for (int o = 1; o < 256; o <<= 1) {
        int u = (t >= o) ? sh[t - o] : 0;
        __syncthreads();
        sh[t] += u;
        __syncthreads();
    }
    int pre = g_boff[b] + sh[t] - s;
    if (base < nNodes) { g_rowstart[base] = pre; g_cursor[base] = pre; }
    if (base + 1 < nNodes) { g_rowstart[base + 1] = pre + d0; g_cursor[base + 1] = pre + d0; }
}

__global__ void scatter_kernel(const int* __restrict__ src,
                               const int* __restrict__ dst, int E) {
    int e = blockIdx.x * blockDim.x + threadIdx.x;
    if (e < E) {
        int d = dst[e];
        int p = atomicAdd(&g_cursor[d], 1);
        g_srcs[p] = src[e];
    }
}

// ---------------------------------------------------------------------------
// Mean aggregation, fp32, one warp per destination node.
// Half-warp per edge: lanes 0-15 take edge i, lanes 16-31 take edge i+1.
// Each lane loads one float4 (16 lanes x 16B = full 256B row). Unroll x2.
__global__ void __launch_bounds__(256) aggregate_kernel(
    const float* __restrict__ hin, int nNodes) {
    int gw = (blockIdx.x * blockDim.x + threadIdx.x) >> 5;
    int lane = threadIdx.x & 31;
    if (gw >= nNodes) return;
    int half = lane >> 4;   // 0 or 1
    int q = lane & 15;      // float4 index within the row
    int start = g_rowstart[gw];
    int deg = g_deg[gw];
    const float4* base = (const float4*)hin;

    float ax = 0.f, ay = 0.f, az = 0.f, aw = 0.f;
    int i = 0;
    for (; i + 4 <= deg; i += 4) {
        int sA = __ldg(&g_srcs[start + i + half]);
        int sB = __ldg(&g_srcs[start + i + 2 + half]);
        float4 a = __ldg(base + sA * 16 + q);
        float4 b = __ldg(base + sB * 16 + q);
        ax += a.x + b.x;
        ay += a.y + b.y;
        az += a.z + b.z;
        aw += a.w + b.w;
    }
    for (; i < deg; i += 2) {
        int idx = i + half;
        if (idx < deg) {
            int s = __ldg(&g_srcs[start + idx]);
            float4 a = __ldg(base + s * 16 + q);
            ax += a.x;
            ay += a.y;
            az += a.z;
            aw += a.w;
        }
    }
    // merge the two half-warps (feature q lives in lanes q and q+16)
    ax += __shfl_xor_sync(0xffffffffu, ax, 16);
    ay += __shfl_xor_sync(0xffffffffu, ay, 16);
    az += __shfl_xor_sync(0xffffffffu, az, 16);
    aw += __shfl_xor_sync(0xffffffffu, aw, 16);

    if (half == 0) {
        float inv = deg > 0 ? 1.0f / (float)deg : 0.f;
        ((float4*)(g_aggr + (size_t)gw * F))[q] =
            make_float4(ax * inv, ay * inv, az * inv, aw * inv);
    }
}

// ---------------------------------------------------------------------------
// Fused dual GEMM with packed f32x2 FMA (identical to R2).
#define WSTRIDE 68

__device__ __forceinline__ unsigned long long pack2(float v) {
    unsigned int u = __float_as_uint(v);
    unsigned long long r;
    asm("mov.b64 %0, {%1, %1};" : "=l"(r) : "r"(u));
    return r;
}

__device__ __forceinline__ void load_weights_T(
    const float* __restrict__ wl, const float* __restrict__ wr,
    float (*Wt)[WSTRIDE], int tid) {
    const float4* wl4 = (const float4*)wl;
    const float4* wr4 = (const float4*)wr;
    for (int i = tid; i < 1024; i += 256) {
        int j = i >> 4;
        int kc = (i & 15) << 2;
        float4 a = __ldg(wl4 + i);
        Wt[kc + 0][j] = a.x; Wt[kc + 1][j] = a.y;
        Wt[kc + 2][j] = a.z; Wt[kc + 3][j] = a.w;
        float4 b = __ldg(wr4 + i);
        Wt[64 + kc + 0][j] = b.x; Wt[64 + kc + 1][j] = b.y;
        Wt[64 + kc + 2][j] = b.z; Wt[64 + kc + 3][j] = b.w;
    }
}

__device__ __forceinline__ void dual_mm_row(
    const float* __restrict__ H, int row, const float (*Wt)[WSTRIDE],
    unsigned long long* acc2) {
    const float4* a4 = (const float4*)(g_aggr + (size_t)row * F);
    const float4* h4 = (const float4*)(H + (size_t)row * F);
#pragma unroll 1
    for (int kk = 0; kk < 8; ++kk) {
        const float4* sp = (kk < 4) ? a4 : h4;
        int base = (kk & 3) * 4;
        float4 v0 = __ldg(sp + base + 0);
        float4 v1 = __ldg(sp + base + 1);
        float4 v2 = __ldg(sp + base + 2);
        float4 v3 = __ldg(sp + base + 3);
        float a[16] = {v0.x, v0.y, v0.z, v0.w, v1.x, v1.y, v1.z, v1.w,
                       v2.x, v2.y, v2.z, v2.w, v3.x, v3.y, v3.z, v3.w};
        int kb = kk * 16;
#pragma unroll
        for (int k = 0; k < 16; ++k) {
            unsigned long long a2 = pack2(a[k]);
            const ulonglong2* wp = (const ulonglong2*)&Wt[kb + k][0];
#pragma unroll
            for (int j4 = 0; j4 < 16; ++j4) {
                ulonglong2 w = wp[j4];
                asm("fma.rn.f32x2 %0, %1, %2, %0;"
                    : "+l"(acc2[2 * j4 + 0]) : "l"(a2), "l"(w.x));
                asm("fma.rn.f32x2 %0, %1, %2, %0;"
                    : "+l"(acc2[2 * j4 + 1]) : "l"(a2), "l"(w.y));
            }
        }
    }
}

__global__ void __launch_bounds__(256, 2) gemm_bn_kernel(
    const float* __restrict__ H,
    const float* __restrict__ wl, const float* __restrict__ wr,
    const float* __restrict__ bl,
    const float* __restrict__ gn, const float* __restrict__ be,
    const float* __restrict__ mn, const float* __restrict__ vr,
    float* __restrict__ out, int nNodes) {
    __shared__ __align__(16) float Wt[128][WSTRIDE];
    __shared__ float s_scale[F];
    __shared__ float s_shift[F];

    int tid = threadIdx.x;
    load_weights_T(wl, wr, Wt, tid);
    if (tid < F) {
        float sc = __ldg(&gn[tid]) * rsqrtf(__ldg(&vr[tid]) + 1e-5f);
        s_scale[tid] = sc;
        s_shift[tid] = (__ldg(&bl[tid]) - __ldg(&mn[tid])) * sc + __ldg(&be[tid]);
    }
    __syncthreads();

    int row = blockIdx.x * 256 + tid;
    if (row >= nNodes) return;

    unsigned long long acc2[32];
#pragma unroll
    for (int j2 = 0; j2 < 32; ++j2) acc2[j2] = 0ull;
    dual_mm_row(H, row, Wt, acc2);

    float* orow = out + (size_t)row * F;
#pragma unroll
    for (int c = 0; c < 16; ++c) {
        unsigned int lo0, hi0, lo1, hi1;
        asm("mov.b64 {%0, %1}, %2;" : "=r"(lo0), "=r"(hi0) : "l"(acc2[2 * c + 0]));
        asm("mov.b64 {%0, %1}, %2;" : "=r"(lo1), "=r"(hi1) : "l"(acc2[2 * c + 1]));
        int j = 4 * c;
        float4 o;
        o.x = fmaxf(fmaf(__uint_as_float(lo0), s_scale[j + 0], s_shift[j + 0]), 0.f);
        o.y = fmaxf(fmaf(__uint_as_float(hi0), s_scale[j + 1], s_shift[j + 1]), 0.f);
        o.z = fmaxf(fmaf(__uint_as_float(lo1), s_scale[j + 2], s_shift[j + 2]), 0.f);
        o.w = fmaxf(fmaf(__uint_as_float(hi1), s_scale[j + 3], s_shift[j + 3]), 0.f);
        *(float4*)&orow[j] = o;
    }
}

// Final layer: dual GEMM, warp-reduce straight into global column sums.
__global__ void __launch_bounds__(256, 2) gemm_final_kernel(
    const float* __restrict__ H,
    const float* __restrict__ wl, const float* __restrict__ wr, int nNodes) {
    __shared__ __align__(16) float Wt[128][WSTRIDE];
    int tid = threadIdx.x;
    load_weights_T(wl, wr, Wt, tid);
    __syncthreads();

    int row = blockIdx.x * 256 + tid;
    bool valid = row < nNodes;

    unsigned long long acc2[32];
#pragma unroll
    for (int j2 = 0; j2 < 32; ++j2) acc2[j2] = 0ull;
    if (valid) dual_mm_row(H, row, Wt, acc2);

    int lane = tid & 31;
#pragma unroll
    for (int j2 = 0; j2 < 32; ++j2) {
        unsigned int lo, hi;
        asm("mov.b64 {%0, %1}, %2;" : "=r"(lo), "=r"(hi) : "l"(acc2[j2]));
        float v0 = __uint_as_float(lo);
        float v1 = __uint_as_float(hi);
#pragma unroll
        for (int o = 16; o > 0; o >>= 1) {
            v0 += __shfl_xor_sync(0xffffffffu, v0, o);
            v1 += __shfl_xor_sync(0xffffffffu, v1, o);
        }
        if (lane == 0) {
            atomicAdd(&g_colsum[2 * j2 + 0], v0);
            atomicAdd(&g_colsum[2 * j2 + 1], v1);
        }
    }
}

// head: mean -> +b_l2 -> Linear(64,64)+ReLU -> Linear(64,1) -> sigmoid
__global__ void head_kernel(const float* __restrict__ bl2,
                            const float* __restrict__ cw1,
                            const float* __restrict__ cb1,
                            const float* __restrict__ cw2,
                            const float* __restrict__ cb2,
                            float* __restrict__ outp, int nNodes) {
    __shared__ float mean[F];
    __shared__ float z[F];
    int t = threadIdx.x;
    mean[t] = g_colsum[t] / (float)nNodes + __ldg(&bl2[t]);
    __syncthreads();
    float s = __ldg(&cb1[t]);
#pragma unroll
    for (int j = 0; j < F; ++j) s = fmaf(mean[j], __ldg(&cw1[t * F + j]), s);
    z[t] = fmaxf(s, 0.f);
    __syncthreads();
    if (t == 0) {
        float o = __ldg(&cb2[0]);
#pragma unroll
        for (int i = 0; i < F; ++i) o = fmaf(z[i], __ldg(&cw2[i]), o);
        outp[0] = 1.f / (1.f + expf(-o));
    }
}

// ---------------------------------------------------------------------------
extern "C" void kernel_launch(void* const* d_in, const int* in_sizes, int n_in,
                              void* d_out, int out_size) {
    const float* x    = (const float*)d_in[0];
    const int*   eidx = (const int*)d_in[1];
    const float* w_l0 = (const float*)d_in[2];
    const float* b_l0 = (const float*)d_in[3];
    const float* w_r0 = (const float*)d_in[4];
    const float* w_l1 = (const float*)d_in[5];
    const float* b_l1 = (const float*)d_in[6];
    const float* w_r1 = (const float*)d_in[7];
    const float* w_l2 = (const float*)d_in[8];
    const float* b_l2 = (const float*)d_in[9];
    const float* w_r2 = (const float*)d_in[10];
    const float* g0   = (const float*)d_in[11];
    const float* be0  = (const float*)d_in[12];
    const float* m0   = (const float*)d_in[13];
    const float* v0   = (const float*)d_in[14];
    const float* g1   = (const float*)d_in[15];
    const float* be1  = (const float*)d_in[16];
    const float* m1   = (const float*)d_in[17];
    const float* v1   = (const float*)d_in[18];
    const float* cw1  = (const float*)d_in[19];
    const float* cb1  = (const float*)d_in[20];
    const float* cw2  = (const float*)d_in[21];
    const float* cb2  = (const float*)d_in[22];
    float* out = (float*)d_out;

    int nN = in_sizes[0] / F;
    int E = in_sizes[1] / 2;
    if (nN > MAXN) nN = MAXN;
    if (E > MAXE) E = MAXE;
    const int* srcp = eidx;
    const int* dstp = eidx + E;

    float *bufA, *bufB;
    cudaGetSymbolAddress((void**)&bufA, g_bufA);
    cudaGetSymbolAddress((void**)&bufB, g_bufB);

    int tb = 256;
    init_kernel<<<(nN + tb - 1) / tb, tb>>>(nN);
    hist_kernel<<<(E + tb - 1) / tb, tb>>>(dstp, E);
    scan_pass1<<<256, 256>>>(nN);
    scan_pass2<<<1, 256>>>();
    scan_pass3<<<256, 256>>>(nN);
    scatter_kernel<<<(E + tb - 1) / tb, tb>>>(srcp, dstp, E);

    int aggBlocks = (nN + 7) / 8;
    int gemmBlocks = (nN + 255) / 256;

    // Layer 0: x -> bufA
    aggregate_kernel<<<aggBlocks, tb>>>(x, nN);
    gemm_bn_kernel<<<gemmBlocks, tb>>>(x, w_l0, w_r0, b_l0, g0, be0, m0, v0,
                                       bufA, nN);
    // Layer 1: bufA -> bufB
    aggregate_kernel<<<aggBlocks, tb>>>(bufA, nN);
    gemm_bn_kernel<<<gemmBlocks, tb>>>(bufA, w_l1, w_r1, b_l1, g1, be1, m1, v1,
                                       bufB, nN);
    // Layer 2: bufB -> column sums directly
    aggregate_kernel<<<aggBlocks, tb>>>(bufB, nN);
    gemm_final_kernel<<<gemmBlocks, tb>>>(bufB, w_l2, w_r2, nN);

    head_kernel<<<1, F>>>(b_l2, cw1, cb1, cw2, cb2, out, nN);
}

// round 7
// speedup vs baseline: 1.2082x; 1.2082x over previous
#include <cuda_runtime.h>
#include <cuda_bf16.h>
#include <math.h>

// ---------------------------------------------------------------------------
// GraphSAGE fraud detector, fp32 (R7): exact R2 pipeline (separate colsum,
// no fused final reduction) + half-warp paired gather in aggregate only.
// ---------------------------------------------------------------------------

#define MAXN 100000
#define MAXE 1600000
#define F 64

__device__ int   g_deg[MAXN];
__device__ int   g_rowstart[MAXN];
__device__ int   g_cursor[MAXN];
__device__ int   g_srcs[MAXE];
__device__ float g_aggr[(size_t)MAXN * F];
__device__ float g_bufA[(size_t)MAXN * F];
__device__ float g_bufB[(size_t)MAXN * F];
__device__ float g_colsum[F];
__device__ int   g_bsum[256];
__device__ int   g_boff[256];

// ---------------------------------------------------------------------------
__global__ void init_kernel(int nNodes) {
    int i = blockIdx.x * blockDim.x + threadIdx.x;
    if (i < nNodes) g_deg[i] = 0;
    if (i < F) g_colsum[i] = 0.f;
}

__global__ void hist_kernel(const int* __restrict__ dst, int E) {
    int e = blockIdx.x * blockDim.x + threadIdx.x;
    if (e < E) atomicAdd(&g_deg[dst[e]], 1);
}

// --- 3-phase parallel exclusive scan over degrees (2 nodes / thread) -------
__global__ void scan_pass1(int nNodes) {
    int t = threadIdx.x, b = blockIdx.x;
    int base = (b * 256 + t) * 2;
    int s = 0;
    if (base < nNodes) s += g_deg[base];
    if (base + 1 < nNodes) s += g_deg[base + 1];
    __shared__ int sh[256];
    sh[t] = s;
    __syncthreads();
    for (int o = 128; o > 0; o >>= 1) {
        if (t < o) sh[t] += sh[t + o];
        __syncthreads();
    }
    if (t == 0) g_bsum[b] = sh[0];
}

__global__ void scan_pass2() {
    __shared__ int sh[256];
    int t = threadIdx.x;
    int v = g_bsum[t];
    sh[t] = v;
    __syncthreads();
    for (int o = 1; o < 256; o <<= 1) {
        int u = (t >= o) ? sh[t - o] : 0;
        __syncthreads();
        sh[t] += u;
        __syncthreads();
    }
    g_boff[t] = sh[t] - v;
}

__global__ void scan_pass3(int nNodes) {
    int t = threadIdx.x, b = blockIdx.x;
    int base = (b * 256 + t) * 2;
    int d0 = (base < nNodes) ? g_deg[base] : 0;
    int d1 = (base + 1 < nNodes) ? g_deg[base + 1] : 0;
    int s = d0 + d1;
    __shared__ int sh[256];
    sh[t] = s;
    __syncthreads();
    for (int o = 1; o < 256; o <<= 1) {
        int u = (t >= o) ? sh[t - o] : 0;
        __syncthreads();
        sh[t] += u;
        __syncthreads();
    }
    int pre = g_boff[b] + sh[t] - s;
    if (base < nNodes) { g_rowstart[base] = pre; g_cursor[base] = pre; }
    if (base + 1 < nNodes) { g_rowstart[base + 1] = pre + d0; g_cursor[base + 1] = pre + d0; }
}

__global__ void scatter_kernel(const int* __restrict__ src,
                               const int* __restrict__ dst, int E) {
    int e = blockIdx.x * blockDim.x + threadIdx.x;
    if (e < E) {
        int d = dst[e];
        int p = atomicAdd(&g_cursor[d], 1);
        g_srcs[p] = src[e];
    }
}

// ---------------------------------------------------------------------------
// Mean aggregation, fp32, one warp per destination node.
// Half-warp per edge: lanes 0-15 take edge i, lanes 16-31 take edge i+1.
// Each lane loads one float4 (16 lanes x 16B = full 256B row). Unroll x2.
__global__ void __launch_bounds__(256) aggregate_kernel(
    const float* __restrict__ hin, int nNodes) {
    int gw = (blockIdx.x * blockDim.x + threadIdx.x) >> 5;
    int lane = threadIdx.x & 31;
    if (gw >= nNodes) return;
    int half = lane >> 4;   // 0 or 1
    int q = lane & 15;      // float4 index within the row
    int start = g_rowstart[gw];
    int deg = g_deg[gw];
    const float4* base = (const float4*)hin;

    float ax = 0.f, ay = 0.f, az = 0.f, aw = 0.f;
    int i = 0;
    for (; i + 4 <= deg; i += 4) {
        int sA = __ldg(&g_srcs[start + i + half]);
        int sB = __ldg(&g_srcs[start + i + 2 + half]);
        float4 a = __ldg(base + sA * 16 + q);
        float4 b = __ldg(base + sB * 16 + q);
        ax += a.x + b.x;
        ay += a.y + b.y;
        az += a.z + b.z;
        aw += a.w + b.w;
    }
    for (; i < deg; i += 2) {
        int idx = i + half;
        if (idx < deg) {
            int s = __ldg(&g_srcs[start + idx]);
            float4 a = __ldg(base + s * 16 + q);
            ax += a.x;
            ay += a.y;
            az += a.z;
            aw += a.w;
        }
    }
    // merge the two half-warps (feature q lives in lanes q and q+16)
    ax += __shfl_xor_sync(0xffffffffu, ax, 16);
    ay += __shfl_xor_sync(0xffffffffu, ay, 16);
    az += __shfl_xor_sync(0xffffffffu, az, 16);
    aw += __shfl_xor_sync(0xffffffffu, aw, 16);

    if (half == 0) {
        float inv = deg > 0 ? 1.0f / (float)deg : 0.f;
        ((float4*)(g_aggr + (size_t)gw * F))[q] =
            make_float4(ax * inv, ay * inv, az * inv, aw * inv);
    }
}

// ---------------------------------------------------------------------------
// Fused dual GEMM with packed f32x2 FMA (identical to R2).
#define WSTRIDE 68

__device__ __forceinline__ unsigned long long pack2(float v) {
    unsigned int u = __float_as_uint(v);
    unsigned long long r;
    asm("mov.b64 %0, {%1, %1};" : "=l"(r) : "r"(u));
    return r;
}

template <bool BN_RELU>
__global__ void __launch_bounds__(256, 2) gemm_kernel(
    const float* __restrict__ H,
    const float* __restrict__ wl, const float* __restrict__ wr,
    const float* __restrict__ bl,
    const float* __restrict__ gn, const float* __restrict__ be,
    const float* __restrict__ mn, const float* __restrict__ vr,
    float* __restrict__ out, int nNodes) {
    __shared__ __align__(16) float Wt[128][WSTRIDE];
    __shared__ float s_scale[F];
    __shared__ float s_shift[F];

    int tid = threadIdx.x;
    const float4* wl4 = (const float4*)wl;
    const float4* wr4 = (const float4*)wr;
    for (int i = tid; i < 1024; i += 256) {  // 1024 float4 per 64x64 matrix
        int j = i >> 4;          // 0..63  (output col)
        int kc = (i & 15) << 2;  // 0..60  (k chunk)
        float4 a = __ldg(wl4 + i);
        Wt[kc + 0][j] = a.x; Wt[kc + 1][j] = a.y;
        Wt[kc + 2][j] = a.z; Wt[kc + 3][j] = a.w;
        float4 b = __ldg(wr4 + i);
        Wt[64 + kc + 0][j] = b.x; Wt[64 + kc + 1][j] = b.y;
        Wt[64 + kc + 2][j] = b.z; Wt[64 + kc + 3][j] = b.w;
    }
    if (BN_RELU && tid < F) {
        float sc = __ldg(&gn[tid]) * rsqrtf(__ldg(&vr[tid]) + 1e-5f);
        s_scale[tid] = sc;
        s_shift[tid] = (__ldg(&bl[tid]) - __ldg(&mn[tid])) * sc + __ldg(&be[tid]);
    }
    __syncthreads();

    int row = blockIdx.x * 256 + tid;
    if (row >= nNodes) return;

    unsigned long long acc2[32];
#pragma unroll
    for (int j2 = 0; j2 < 32; ++j2) acc2[j2] = 0ull;

    const float4* a4 = (const float4*)(g_aggr + (size_t)row * F);
    const float4* h4 = (const float4*)(H + (size_t)row * F);
#pragma unroll 1
    for (int kk = 0; kk < 8; ++kk) {
        const float4* sp = (kk < 4) ? a4 : h4;
        int base = (kk & 3) * 4;
        float4 v0 = __ldg(sp + base + 0);
        float4 v1 = __ldg(sp + base + 1);
        float4 v2 = __ldg(sp + base + 2);
        float4 v3 = __ldg(sp + base + 3);
        float a[16] = {v0.x, v0.y, v0.z, v0.w, v1.x, v1.y, v1.z, v1.w,
                       v2.x, v2.y, v2.z, v2.w, v3.x, v3.y, v3.z, v3.w};
        int kb = kk * 16;
#pragma unroll
        for (int k = 0; k < 16; ++k) {
            unsigned long long a2 = pack2(a[k]);
            const ulonglong2* wp = (const ulonglong2*)&Wt[kb + k][0];
#pragma unroll
            for (int j4 = 0; j4 < 16; ++j4) {
                ulonglong2 w = wp[j4];
                asm("fma.rn.f32x2 %0, %1, %2, %0;"
                    : "+l"(acc2[2 * j4 + 0]) : "l"(a2), "l"(w.x));
                asm("fma.rn.f32x2 %0, %1, %2, %0;"
                    : "+l"(acc2[2 * j4 + 1]) : "l"(a2), "l"(w.y));
            }
        }
    }

    float o[F];
#pragma unroll
    for (int j2 = 0; j2 < 32; ++j2) {
        unsigned int lo, hi;
        asm("mov.b64 {%0, %1}, %2;" : "=r"(lo), "=r"(hi) : "l"(acc2[j2]));
        float x0 = __uint_as_float(lo);
        float x1 = __uint_as_float(hi);
        if (BN_RELU) {
            x0 = fmaxf(fmaf(x0, s_scale[2 * j2 + 0], s_shift[2 * j2 + 0]), 0.f);
            x1 = fmaxf(fmaf(x1, s_scale[2 * j2 + 1], s_shift[2 * j2 + 1]), 0.f);
        }
        o[2 * j2 + 0] = x0;
        o[2 * j2 + 1] = x1;
    }
    float* orow = out + (size_t)row * F;
#pragma unroll
    for (int j = 0; j < F; j += 4)
        *(float4*)&orow[j] = make_float4(o[j], o[j + 1], o[j + 2], o[j + 3]);
}

// ---------------------------------------------------------------------------
// Column sums of final layer output (bias deferred to head kernel).
__global__ void colsum_kernel(const float* __restrict__ hin, int nNodes) {
    int t = blockIdx.x * blockDim.x + threadIdx.x;
    int col = t & 63;
    int r = t >> 6;
    int stride = (gridDim.x * blockDim.x) >> 6;
    float s = 0.f;
    for (; r < nNodes; r += stride) s += __ldg(&hin[(size_t)r * F + col]);
    atomicAdd(&g_colsum[col], s);
}

// head: mean -> +b_l2 -> Linear(64,64)+ReLU -> Linear(64,1) -> sigmoid
__global__ void head_kernel(const float* __restrict__ bl2,
                            const float* __restrict__ cw1,
                            const float* __restrict__ cb1,
                            const float* __restrict__ cw2,
                            const float* __restrict__ cb2,
                            float* __restrict__ outp, int nNodes) {
    __shared__ float mean[F];
    __shared__ float z[F];
    int t = threadIdx.x;
    mean[t] = g_colsum[t] / (float)nNodes + __ldg(&bl2[t]);
    __syncthreads();
    float s = __ldg(&cb1[t]);
#pragma unroll
    for (int j = 0; j < F; ++j) s = fmaf(mean[j], __ldg(&cw1[t * F + j]), s);
    z[t] = fmaxf(s, 0.f);
    __syncthreads();
    if (t == 0) {
        float o = __ldg(&cb2[0]);
#pragma unroll
        for (int i = 0; i < F; ++i) o = fmaf(z[i], __ldg(&cw2[i]), o);
        outp[0] = 1.f / (1.f + expf(-o));
    }
}

// ---------------------------------------------------------------------------
extern "C" void kernel_launch(void* const* d_in, const int* in_sizes, int n_in,
                              void* d_out, int out_size) {
    const float* x    = (const float*)d_in[0];
    const int*   eidx = (const int*)d_in[1];
    const float* w_l0 = (const float*)d_in[2];
    const float* b_l0 = (const float*)d_in[3];
    const float* w_r0 = (const float*)d_in[4];
    const float* w_l1 = (const float*)d_in[5];
    const float* b_l1 = (const float*)d_in[6];
    const float* w_r1 = (const float*)d_in[7];
    const float* w_l2 = (const float*)d_in[8];
    const float* b_l2 = (const float*)d_in[9];
    const float* w_r2 = (const float*)d_in[10];
    const float* g0   = (const float*)d_in[11];
    const float* be0  = (const float*)d_in[12];
    const float* m0   = (const float*)d_in[13];
    const float* v0   = (const float*)d_in[14];
    const float* g1   = (const float*)d_in[15];
    const float* be1  = (const float*)d_in[16];
    const float* m1   = (const float*)d_in[17];
    const float* v1   = (const float*)d_in[18];
    const float* cw1  = (const float*)d_in[19];
    const float* cb1  = (const float*)d_in[20];
    const float* cw2  = (const float*)d_in[21];
    const float* cb2  = (const float*)d_in[22];
    float* out = (float*)d_out;

    int nN = in_sizes[0] / F;
    int E = in_sizes[1] / 2;
    if (nN > MAXN) nN = MAXN;
    if (E > MAXE) E = MAXE;
    const int* srcp = eidx;
    const int* dstp = eidx + E;

    float *bufA, *bufB;
    cudaGetSymbolAddress((void**)&bufA, g_bufA);
    cudaGetSymbolAddress((void**)&bufB, g_bufB);

    int tb = 256;
    init_kernel<<<(nN + tb - 1) / tb, tb>>>(nN);
    hist_kernel<<<(E + tb - 1) / tb, tb>>>(dstp, E);
    scan_pass1<<<256, 256>>>(nN);
    scan_pass2<<<1, 256>>>();
    scan_pass3<<<256, 256>>>(nN);
    scatter_kernel<<<(E + tb - 1) / tb, tb>>>(srcp, dstp, E);

    int aggBlocks = (nN + 7) / 8;           // warp per node, 8 warps/block
    int gemmBlocks = (nN + 255) / 256;

    // Layer 0: x -> bufA
    aggregate_kernel<<<aggBlocks, tb>>>(x, nN);
    gemm_kernel<true><<<gemmBlocks, tb>>>(x, w_l0, w_r0, b_l0, g0, be0, m0, v0,
                                          bufA, nN);
    // Layer 1: bufA -> bufB
    aggregate_kernel<<<aggBlocks, tb>>>(bufA, nN);
    gemm_kernel<true><<<gemmBlocks, tb>>>(bufA, w_l1, w_r1, b_l1, g1, be1, m1,
                                          v1, bufB, nN);
    // Layer 2: bufB -> bufA (no BN/ReLU, bias deferred)
    aggregate_kernel<<<aggBlocks, tb>>>(bufB, nN);
    gemm_kernel<false><<<gemmBlocks, tb>>>(bufB, w_l2, w_r2, b_l2, nullptr,
                                           nullptr, nullptr, nullptr, bufA, nN);

    colsum_kernel<<<256, tb>>>(bufA, nN);
    head_kernel<<<1, F>>>(b_l2, cw1, cb1, cw2, cb2, out, nN);
}

// round 8
// speedup vs baseline: 1.4021x; 1.1605x over previous
#include <cuda_runtime.h>
#include <cuda_bf16.h>
#include <math.h>

// ---------------------------------------------------------------------------
// GraphSAGE fraud detector (R8): R7 pipeline with the dual GEMM moved onto
// tensor cores (mma.sync m16n8k8 tf32). Aggregate/CSR/colsum/head unchanged.
// ---------------------------------------------------------------------------

#define MAXN 100000
#define MAXE 1600000
#define F 64

__device__ int   g_deg[MAXN];
__device__ int   g_rowstart[MAXN];
__device__ int   g_cursor[MAXN];
__device__ int   g_srcs[MAXE];
__device__ float g_aggr[(size_t)MAXN * F];
__device__ float g_bufA[(size_t)MAXN * F];
__device__ float g_bufB[(size_t)MAXN * F];
__device__ float g_colsum[F];
__device__ int   g_bsum[256];
__device__ int   g_boff[256];

// ---------------------------------------------------------------------------
__global__ void init_kernel(int nNodes) {
    int i = blockIdx.x * blockDim.x + threadIdx.x;
    if (i < nNodes) g_deg[i] = 0;
    if (i < F) g_colsum[i] = 0.f;
}

__global__ void hist_kernel(const int* __restrict__ dst, int E) {
    int e = blockIdx.x * blockDim.x + threadIdx.x;
    if (e < E) atomicAdd(&g_deg[dst[e]], 1);
}

// --- 3-phase parallel exclusive scan over degrees (2 nodes / thread) -------
__global__ void scan_pass1(int nNodes) {
    int t = threadIdx.x, b = blockIdx.x;
    int base = (b * 256 + t) * 2;
    int s = 0;
    if (base < nNodes) s += g_deg[base];
    if (base + 1 < nNodes) s += g_deg[base + 1];
    __shared__ int sh[256];
    sh[t] = s;
    __syncthreads();
    for (int o = 128; o > 0; o >>= 1) {
        if (t < o) sh[t] += sh[t + o];
        __syncthreads();
    }
    if (t == 0) g_bsum[b] = sh[0];
}

__global__ void scan_pass2() {
    __shared__ int sh[256];
    int t = threadIdx.x;
    int v = g_bsum[t];
    sh[t] = v;
    __syncthreads();
    for (int o = 1; o < 256; o <<= 1) {
        int u = (t >= o) ? sh[t - o] : 0;
        __syncthreads();
        sh[t] += u;
        __syncthreads();
    }
    g_boff[t] = sh[t] - v;
}

__global__ void scan_pass3(int nNodes) {
    int t = threadIdx.x, b = blockIdx.x;
    int base = (b * 256 + t) * 2;
    int d0 = (base < nNodes) ? g_deg[base] : 0;
    int d1 = (base + 1 < nNodes) ? g_deg[base + 1] : 0;
    int s = d0 + d1;
    __shared__ int sh[256];
    sh[t] = s;
    __syncthreads();
    for (int o = 1; o < 256; o <<= 1) {
        int u = (t >= o) ? sh[t - o] : 0;
        __syncthreads();
        sh[t] += u;
        __syncthreads();
    }
    int pre = g_boff[b] + sh[t] - s;
    if (base < nNodes) { g_rowstart[base] = pre; g_cursor[base] = pre; }
    if (base + 1 < nNodes) { g_rowstart[base + 1] = pre + d0; g_cursor[base + 1] = pre + d0; }
}

__global__ void scatter_kernel(const int* __restrict__ src,
                               const int* __restrict__ dst, int E) {
    int e = blockIdx.x * blockDim.x + threadIdx.x;
    if (e < E) {
        int d = dst[e];
        int p = atomicAdd(&g_cursor[d], 1);
        g_srcs[p] = src[e];
    }
}

// ---------------------------------------------------------------------------
// Mean aggregation, fp32, one warp per destination node (R7, unchanged).
__global__ void __launch_bounds__(256) aggregate_kernel(
    const float* __restrict__ hin, int nNodes) {
    int gw = (blockIdx.x * blockDim.x + threadIdx.x) >> 5;
    int lane = threadIdx.x & 31;
    if (gw >= nNodes) return;
    int half = lane >> 4;
    int q = lane & 15;
    int start = g_rowstart[gw];
    int deg = g_deg[gw];
    const float4* base = (const float4*)hin;

    float ax = 0.f, ay = 0.f, az = 0.f, aw = 0.f;
    int i = 0;
    for (; i + 4 <= deg; i += 4) {
        int sA = __ldg(&g_srcs[start + i + half]);
        int sB = __ldg(&g_srcs[start + i + 2 + half]);
        float4 a = __ldg(base + sA * 16 + q);
        float4 b = __ldg(base + sB * 16 + q);
        ax += a.x + b.x;
        ay += a.y + b.y;
        az += a.z + b.z;
        aw += a.w + b.w;
    }
    for (; i < deg; i += 2) {
        int idx = i + half;
        if (idx < deg) {
            int s = __ldg(&g_srcs[start + idx]);
            float4 a = __ldg(base + s * 16 + q);
            ax += a.x;
            ay += a.y;
            az += a.z;
            aw += a.w;
        }
    }
    ax += __shfl_xor_sync(0xffffffffu, ax, 16);
    ay += __shfl_xor_sync(0xffffffffu, ay, 16);
    az += __shfl_xor_sync(0xffffffffu, az, 16);
    aw += __shfl_xor_sync(0xffffffffu, aw, 16);

    if (half == 0) {
        float inv = deg > 0 ? 1.0f / (float)deg : 0.f;
        ((float4*)(g_aggr + (size_t)gw * F))[q] =
            make_float4(ax * inv, ay * inv, az * inv, aw * inv);
    }
}

// ---------------------------------------------------------------------------
// Tensor-core dual GEMM: out[r][j] = sum_k [aggr(r)|H(r)][k] * Wt[k][j]
// via mma.sync.aligned.m16n8k8 tf32. Block: 128 thr / 4 warps, tile M=64.
#define AS_STRIDE 132   // 128 + 4 pad: A-frag bank = 4q+r, conflict-free
#define BS_STRIDE 72    // 64 + 8 pad:  B-frag bank = 8r+q, conflict-free
#define AS_FLOATS (64 * AS_STRIDE)
#define BS_FLOATS (128 * BS_STRIDE)
#define GEMM_SMEM_BYTES ((AS_FLOATS + BS_FLOATS + 2 * F) * 4)

__device__ __forceinline__ float tf32f(float x) {
    unsigned int u;
    asm("cvt.rna.tf32.f32 %0, %1;" : "=r"(u) : "f"(x));
    return __uint_as_float(u);
}

__device__ __forceinline__ void mma_tf32(float* c, unsigned int a0,
                                         unsigned int a1, unsigned int a2,
                                         unsigned int a3, unsigned int b0,
                                         unsigned int b1) {
    asm("mma.sync.aligned.m16n8k8.row.col.f32.tf32.tf32.f32 "
        "{%0,%1,%2,%3}, {%4,%5,%6,%7}, {%8,%9}, {%0,%1,%2,%3};"
        : "+f"(c[0]), "+f"(c[1]), "+f"(c[2]), "+f"(c[3])
        : "r"(a0), "r"(a1), "r"(a2), "r"(a3), "r"(b0), "r"(b1));
}

template <bool BN_RELU>
__global__ void __launch_bounds__(128) gemm_mma_kernel(
    const float* __restrict__ H,
    const float* __restrict__ wl, const float* __restrict__ wr,
    const float* __restrict__ bl,
    const float* __restrict__ gn, const float* __restrict__ be,
    const float* __restrict__ mn, const float* __restrict__ vr,
    float* __restrict__ out, int nNodes) {
    extern __shared__ float smem[];
    float* As = smem;                         // [64][AS_STRIDE]
    float* Bs = smem + AS_FLOATS;             // [128][BS_STRIDE]
    float* s_scale = Bs + BS_FLOATS;          // [64]
    float* s_shift = s_scale + F;             // [64]

    int tid = threadIdx.x;
    int warp = tid >> 5;
    int lane = tid & 31;
    int row0 = blockIdx.x * 64;

    // Stage weights transposed, tf32-rounded: Bs[k][j]=Wl[j][k], Bs[64+k][j]=Wr[j][k]
    const float4* wl4 = (const float4*)wl;
    const float4* wr4 = (const float4*)wr;
    for (int i = tid; i < 1024; i += 128) {
        int j = i >> 4;
        int kc = (i & 15) << 2;
        float4 a = __ldg(wl4 + i);
        Bs[(kc + 0) * BS_STRIDE + j] = tf32f(a.x);
        Bs[(kc + 1) * BS_STRIDE + j] = tf32f(a.y);
        Bs[(kc + 2) * BS_STRIDE + j] = tf32f(a.z);
        Bs[(kc + 3) * BS_STRIDE + j] = tf32f(a.w);
        float4 b = __ldg(wr4 + i);
        Bs[(64 + kc + 0) * BS_STRIDE + j] = tf32f(b.x);
        Bs[(64 + kc + 1) * BS_STRIDE + j] = tf32f(b.y);
        Bs[(64 + kc + 2) * BS_STRIDE + j] = tf32f(b.z);
        Bs[(64 + kc + 3) * BS_STRIDE + j] = tf32f(b.w);
    }
    if (BN_RELU && tid < F) {
        float sc = __ldg(&gn[tid]) * rsqrtf(__ldg(&vr[tid]) + 1e-5f);
        s_scale[tid] = sc;
        s_shift[tid] = (__ldg(&bl[tid]) - __ldg(&mn[tid])) * sc + __ldg(&be[tid]);
    }

    // Stage A = [aggr(row) | H(row)] as tf32: As[row][0:64]=aggr, [64:128]=H
    for (int idx = tid; idx < 64 * 32; idx += 128) {
        int row = idx >> 5;        // 0..63
        int c4 = idx & 31;         // float4 index within 128 floats
        int grow = row0 + row;
        float4 v = make_float4(0.f, 0.f, 0.f, 0.f);
        if (grow < nNodes) {
            const float4* src = (c4 < 16)
                ? (const float4*)(g_aggr + (size_t)grow * F) + c4
                : (const float4*)(H + (size_t)grow * F) + (c4 - 16);
            v = __ldg(src);
        }
        float* dstp = As + row * AS_STRIDE + c4 * 4;
        dstp[0] = tf32f(v.x);
        dstp[1] = tf32f(v.y);
        dstp[2] = tf32f(v.z);
        dstp[3] = tf32f(v.w);
    }
    __syncthreads();

    // Warp computes rows [16*warp, 16*warp+16) x all 64 cols, K=128.
    int q = lane >> 2;   // 0..7
    int r = lane & 3;    // 0..3
    float c[8][4];
#pragma unroll
    for (int n = 0; n < 8; ++n)
#pragma unroll
        for (int t = 0; t < 4; ++t) c[n][t] = 0.f;

    int arow = warp * 16;
#pragma unroll 4
    for (int kt = 0; kt < 16; ++kt) {
        int k0 = kt * 8;
        const float* Ab = As + (arow + q) * AS_STRIDE + k0 + r;
        unsigned int a0 = __float_as_uint(Ab[0]);
        unsigned int a1 = __float_as_uint(Ab[8 * AS_STRIDE]);
        unsigned int a2 = __float_as_uint(Ab[4]);
        unsigned int a3 = __float_as_uint(Ab[8 * AS_STRIDE + 4]);
#pragma unroll
        for (int n = 0; n < 8; ++n) {
            const float* Bb = Bs + (k0 + r) * BS_STRIDE + n * 8 + q;
            unsigned int b0 = __float_as_uint(Bb[0]);
            unsigned int b1 = __float_as_uint(Bb[4 * BS_STRIDE]);
            mma_tf32(c[n], a0, a1, a2, a3, b0, b1);
        }
    }

    // Epilogue: thread holds rows (arow+q, arow+q+8), cols n*8 + 2r + {0,1}.
    int gr0 = row0 + arow + q;
    int gr1 = gr0 + 8;
#pragma unroll
    for (int n = 0; n < 8; ++n) {
        int j = n * 8 + 2 * r;
        float x0 = c[n][0], x1 = c[n][1], x2 = c[n][2], x3 = c[n][3];
        if (BN_RELU) {
            float sc0 = s_scale[j], sh0 = s_shift[j];
            float sc1 = s_scale[j + 1], sh1 = s_shift[j + 1];
            x0 = fmaxf(fmaf(x0, sc0, sh0), 0.f);
            x1 = fmaxf(fmaf(x1, sc1, sh1), 0.f);
            x2 = fmaxf(fmaf(x2, sc0, sh0), 0.f);
            x3 = fmaxf(fmaf(x3, sc1, sh1), 0.f);
        }
        if (gr0 < nNodes)
            *(float2*)(out + (size_t)gr0 * F + j) = make_float2(x0, x1);
        if (gr1 < nNodes)
            *(float2*)(out + (size_t)gr1 * F + j) = make_float2(x2, x3);
    }
}

// ---------------------------------------------------------------------------
// Column sums of final layer output (bias deferred to head kernel).
__global__ void colsum_kernel(const float* __restrict__ hin, int nNodes) {
    int t = blockIdx.x * blockDim.x + threadIdx.x;
    int col = t & 63;
    int r = t >> 6;
    int stride = (gridDim.x * blockDim.x) >> 6;
    float s = 0.f;
    for (; r < nNodes; r += stride) s += __ldg(&hin[(size_t)r * F + col]);
    atomicAdd(&g_colsum[col], s);
}

// head: mean -> +b_l2 -> Linear(64,64)+ReLU -> Linear(64,1) -> sigmoid
__global__ void head_kernel(const float* __restrict__ bl2,
                            const float* __restrict__ cw1,
                            const float* __restrict__ cb1,
                            const float* __restrict__ cw2,
                            const float* __restrict__ cb2,
                            float* __restrict__ outp, int nNodes) {
    __shared__ float mean[F];
    __shared__ float z[F];
    int t = threadIdx.x;
    mean[t] = g_colsum[t] / (float)nNodes + __ldg(&bl2[t]);
    __syncthreads();
    float s = __ldg(&cb1[t]);
#pragma unroll
    for (int j = 0; j < F; ++j) s = fmaf(mean[j], __ldg(&cw1[t * F + j]), s);
    z[t] = fmaxf(s, 0.f);
    __syncthreads();
    if (t == 0) {
        float o = __ldg(&cb2[0]);
#pragma unroll
        for (int i = 0; i < F; ++i) o = fmaf(z[i], __ldg(&cw2[i]), o);
        outp[0] = 1.f / (1.f + expf(-o));
    }
}

// ---------------------------------------------------------------------------
extern "C" void kernel_launch(void* const* d_in, const int* in_sizes, int n_in,
                              void* d_out, int out_size) {
    const float* x    = (const float*)d_in[0];
    const int*   eidx = (const int*)d_in[1];
    const float* w_l0 = (const float*)d_in[2];
    const float* b_l0 = (const float*)d_in[3];
    const float* w_r0 = (const float*)d_in[4];
    const float* w_l1 = (const float*)d_in[5];
    const float* b_l1 = (const float*)d_in[6];
    const float* w_r1 = (const float*)d_in[7];
    const float* w_l2 = (const float*)d_in[8];
    const float* b_l2 = (const float*)d_in[9];
    const float* w_r2 = (const float*)d_in[10];
    const float* g0   = (const float*)d_in[11];
    const float* be0  = (const float*)d_in[12];
    const float* m0   = (const float*)d_in[13];
    const float* v0   = (const float*)d_in[14];
    const float* g1   = (const float*)d_in[15];
    const float* be1  = (const float*)d_in[16];
    const float* m1   = (const float*)d_in[17];
    const float* v1   = (const float*)d_in[18];
    const float* cw1  = (const float*)d_in[19];
    const float* cb1  = (const float*)d_in[20];
    const float* cw2  = (const float*)d_in[21];
    const float* cb2  = (const float*)d_in[22];
    float* out = (float*)d_out;

    int nN = in_sizes[0] / F;
    int E = in_sizes[1] / 2;
    if (nN > MAXN) nN = MAXN;
    if (E > MAXE) E = MAXE;
    const int* srcp = eidx;
    const int* dstp = eidx + E;

    float *bufA, *bufB;
    cudaGetSymbolAddress((void**)&bufA, g_bufA);
    cudaGetSymbolAddress((void**)&bufB, g_bufB);

    cudaFuncSetAttribute(gemm_mma_kernel<true>,
                         cudaFuncAttributeMaxDynamicSharedMemorySize,
                         GEMM_SMEM_BYTES);
    cudaFuncSetAttribute(gemm_mma_kernel<false>,
                         cudaFuncAttributeMaxDynamicSharedMemorySize,
                         GEMM_SMEM_BYTES);

    int tb = 256;
    init_kernel<<<(nN + tb - 1) / tb, tb>>>(nN);
    hist_kernel<<<(E + tb - 1) / tb, tb>>>(dstp, E);
    scan_pass1<<<256, 256>>>(nN);
    scan_pass2<<<1, 256>>>();
    scan_pass3<<<256, 256>>>(nN);
    scatter_kernel<<<(E + tb - 1) / tb, tb>>>(srcp, dstp, E);

    int aggBlocks = (nN + 7) / 8;           // warp per node, 8 warps/block
    int gemmBlocks = (nN + 63) / 64;        // 64-row tiles

    // Layer 0: x -> bufA
    aggregate_kernel<<<aggBlocks, tb>>>(x, nN);
    gemm_mma_kernel<true><<<gemmBlocks, 128, GEMM_SMEM_BYTES>>>(
        x, w_l0, w_r0, b_l0, g0, be0, m0, v0, bufA, nN);
    // Layer 1: bufA -> bufB
    aggregate_kernel<<<aggBlocks, tb>>>(bufA, nN);
    gemm_mma_kernel<true><<<gemmBlocks, 128, GEMM_SMEM_BYTES>>>(
        bufA, w_l1, w_r1, b_l1, g1, be1, m1, v1, bufB, nN);
    // Layer 2: bufB -> bufA (no BN/ReLU, bias deferred)
    aggregate_kernel<<<aggBlocks, tb>>>(bufB, nN);
    gemm_mma_kernel<false><<<gemmBlocks, 128, GEMM_SMEM_BYTES>>>(
        bufB, w_l2, w_r2, b_l2, nullptr, nullptr, nullptr, nullptr, bufA, nN);

    colsum_kernel<<<256, tb>>>(bufA, nN);
    head_kernel<<<1, F>>>(b_l2, cw1, cb1, cw2, cb2, out, nN);
}

// round 9
// speedup vs baseline: 1.4027x; 1.0004x over previous
#include <cuda_runtime.h>
#include <cuda_bf16.h>
#include <math.h>

// ---------------------------------------------------------------------------
// GraphSAGE fraud detector (R9): R8 + MLP-4 aggregate (8 edges/iter),
// merged scan (2 passes), memset-based init.
// ---------------------------------------------------------------------------

#define MAXN 100000
#define MAXE 1600000
#define F 64

__device__ int   g_deg[MAXN];
__device__ int   g_rowstart[MAXN];
__device__ int   g_cursor[MAXN];
__device__ int   g_srcs[MAXE];
__device__ float g_aggr[(size_t)MAXN * F];
__device__ float g_bufA[(size_t)MAXN * F];
__device__ float g_bufB[(size_t)MAXN * F];
__device__ float g_colsum[F];
__device__ int   g_bsum[256];

// ---------------------------------------------------------------------------
__global__ void hist_kernel(const int* __restrict__ dst, int E) {
    int e = blockIdx.x * blockDim.x + threadIdx.x;
    if (e < E) atomicAdd(&g_deg[dst[e]], 1);
}

// --- 2-phase parallel exclusive scan over degrees (2 nodes / thread) -------
__global__ void scan_pass1(int nNodes) {
    int t = threadIdx.x, b = blockIdx.x;
    int base = (b * 256 + t) * 2;
    int s = 0;
    if (base < nNodes) s += g_deg[base];
    if (base + 1 < nNodes) s += g_deg[base + 1];
    __shared__ int sh[256];
    sh[t] = s;
    __syncthreads();
    for (int o = 128; o > 0; o >>= 1) {
        if (t < o) sh[t] += sh[t + o];
        __syncthreads();
    }
    if (t == 0) g_bsum[b] = sh[0];
}

// pass2 merged in: every block scans the 256 block sums itself.
__global__ void scan_pass3(int nNodes) {
    __shared__ int sb[256];
    __shared__ int sh[256];
    int t = threadIdx.x, b = blockIdx.x;
    sb[t] = g_bsum[t];
    __syncthreads();
    for (int o = 1; o < 256; o <<= 1) {
        int u = (t >= o) ? sb[t - o] : 0;
        __syncthreads();
        sb[t] += u;
        __syncthreads();
    }
    int boff = (b > 0) ? sb[b - 1] : 0;

    int base = (b * 256 + t) * 2;
    int d0 = (base < nNodes) ? g_deg[base] : 0;
    int d1 = (base + 1 < nNodes) ? g_deg[base + 1] : 0;
    int s = d0 + d1;
    sh[t] = s;
    __syncthreads();
    for (int o = 1; o < 256; o <<= 1) {
        int u = (t >= o) ? sh[t - o] : 0;
        __syncthreads();
        sh[t] += u;
        __syncthreads();
    }
    int pre = boff + sh[t] - s;
    if (base < nNodes) { g_rowstart[base] = pre; g_cursor[base] = pre; }
    if (base + 1 < nNodes) { g_rowstart[base + 1] = pre + d0; g_cursor[base + 1] = pre + d0; }
}

__global__ void scatter_kernel(const int* __restrict__ src,
                               const int* __restrict__ dst, int E) {
    int e = blockIdx.x * blockDim.x + threadIdx.x;
    if (e < E) {
        int d = dst[e];
        int p = atomicAdd(&g_cursor[d], 1);
        g_srcs[p] = src[e];
    }
}

// ---------------------------------------------------------------------------
// Mean aggregation, fp32, one warp per destination node.
// Half-warp per edge group: half h takes 4 contiguous edges [i+4h, i+4h+4),
// issuing 4 independent row LDG.128s (MLP=4). Merge halves via shfl(16).
__global__ void __launch_bounds__(256) aggregate_kernel(
    const float* __restrict__ hin, int nNodes) {
    int gw = (blockIdx.x * blockDim.x + threadIdx.x) >> 5;
    int lane = threadIdx.x & 31;
    if (gw >= nNodes) return;
    int half = lane >> 4;
    int q = lane & 15;
    int start = g_rowstart[gw];
    int deg = g_deg[gw];
    const float4* base = (const float4*)hin;

    float ax = 0.f, ay = 0.f, az = 0.f, aw = 0.f;
    int i = 0;
    for (; i + 8 <= deg; i += 8) {
        int b0 = start + i + 4 * half;
        int s0 = __ldg(&g_srcs[b0 + 0]);
        int s1 = __ldg(&g_srcs[b0 + 1]);
        int s2 = __ldg(&g_srcs[b0 + 2]);
        int s3 = __ldg(&g_srcs[b0 + 3]);
        float4 r0 = __ldg(base + s0 * 16 + q);
        float4 r1 = __ldg(base + s1 * 16 + q);
        float4 r2 = __ldg(base + s2 * 16 + q);
        float4 r3 = __ldg(base + s3 * 16 + q);
        ax += (r0.x + r1.x) + (r2.x + r3.x);
        ay += (r0.y + r1.y) + (r2.y + r3.y);
        az += (r0.z + r1.z) + (r2.z + r3.z);
        aw += (r0.w + r1.w) + (r2.w + r3.w);
    }
    for (; i < deg; i += 2) {
        int idx = i + half;
        if (idx < deg) {
            int s = __ldg(&g_srcs[start + idx]);
            float4 a = __ldg(base + s * 16 + q);
            ax += a.x;
            ay += a.y;
            az += a.z;
            aw += a.w;
        }
    }
    ax += __shfl_xor_sync(0xffffffffu, ax, 16);
    ay += __shfl_xor_sync(0xffffffffu, ay, 16);
    az += __shfl_xor_sync(0xffffffffu, az, 16);
    aw += __shfl_xor_sync(0xffffffffu, aw, 16);

    if (half == 0) {
        float inv = deg > 0 ? 1.0f / (float)deg : 0.f;
        ((float4*)(g_aggr + (size_t)gw * F))[q] =
            make_float4(ax * inv, ay * inv, az * inv, aw * inv);
    }
}

// ---------------------------------------------------------------------------
// Tensor-core dual GEMM (identical to R8): mma.sync m16n8k8 tf32.
#define AS_STRIDE 132
#define BS_STRIDE 72
#define AS_FLOATS (64 * AS_STRIDE)
#define BS_FLOATS (128 * BS_STRIDE)
#define GEMM_SMEM_BYTES ((AS_FLOATS + BS_FLOATS + 2 * F) * 4)

__device__ __forceinline__ float tf32f(float x) {
    unsigned int u;
    asm("cvt.rna.tf32.f32 %0, %1;" : "=r"(u) : "f"(x));
    return __uint_as_float(u);
}

__device__ __forceinline__ void mma_tf32(float* c, unsigned int a0,
                                         unsigned int a1, unsigned int a2,
                                         unsigned int a3, unsigned int b0,
                                         unsigned int b1) {
    asm("mma.sync.aligned.m16n8k8.row.col.f32.tf32.tf32.f32 "
        "{%0,%1,%2,%3}, {%4,%5,%6,%7}, {%8,%9}, {%0,%1,%2,%3};"
        : "+f"(c[0]), "+f"(c[1]), "+f"(c[2]), "+f"(c[3])
        : "r"(a0), "r"(a1), "r"(a2), "r"(a3), "r"(b0), "r"(b1));
}

template <bool BN_RELU>
__global__ void __launch_bounds__(128) gemm_mma_kernel(
    const float* __restrict__ H,
    const float* __restrict__ wl, const float* __restrict__ wr,
    const float* __restrict__ bl,
    const float* __restrict__ gn, const float* __restrict__ be,
    const float* __restrict__ mn, const float* __restrict__ vr,
    float* __restrict__ out, int nNodes) {
    extern __shared__ float smem[];
    float* As = smem;
    float* Bs = smem + AS_FLOATS;
    float* s_scale = Bs + BS_FLOATS;
    float* s_shift = s_scale + F;

    int tid = threadIdx.x;
    int warp = tid >> 5;
    int lane = tid & 31;
    int row0 = blockIdx.x * 64;

    const float4* wl4 = (const float4*)wl;
    const float4* wr4 = (const float4*)wr;
    for (int i = tid; i < 1024; i += 128) {
        int j = i >> 4;
        int kc = (i & 15) << 2;
        float4 a = __ldg(wl4 + i);
        Bs[(kc + 0) * BS_STRIDE + j] = tf32f(a.x);
        Bs[(kc + 1) * BS_STRIDE + j] = tf32f(a.y);
        Bs[(kc + 2) * BS_STRIDE + j] = tf32f(a.z);
        Bs[(kc + 3) * BS_STRIDE + j] = tf32f(a.w);
        float4 b = __ldg(wr4 + i);
        Bs[(64 + kc + 0) * BS_STRIDE + j] = tf32f(b.x);
        Bs[(64 + kc + 1) * BS_STRIDE + j] = tf32f(b.y);
        Bs[(64 + kc + 2) * BS_STRIDE + j] = tf32f(b.z);
        Bs[(64 + kc + 3) * BS_STRIDE + j] = tf32f(b.w);
    }
    if (BN_RELU && tid < F) {
        float sc = __ldg(&gn[tid]) * rsqrtf(__ldg(&vr[tid]) + 1e-5f);
        s_scale[tid] = sc;
        s_shift[tid] = (__ldg(&bl[tid]) - __ldg(&mn[tid])) * sc + __ldg(&be[tid]);
    }

    for (int idx = tid; idx < 64 * 32; idx += 128) {
        int row = idx >> 5;
        int c4 = idx & 31;
        int grow = row0 + row;
        float4 v = make_float4(0.f, 0.f, 0.f, 0.f);
        if (grow < nNodes) {
            const float4* src = (c4 < 16)
                ? (const float4*)(g_aggr + (size_t)grow * F) + c4
                : (const float4*)(H + (size_t)grow * F) + (c4 - 16);
            v = __ldg(src);
        }
        float* dstp = As + row * AS_STRIDE + c4 * 4;
        dstp[0] = tf32f(v.x);
        dstp[1] = tf32f(v.y);
        dstp[2] = tf32f(v.z);
        dstp[3] = tf32f(v.w);
    }
    __syncthreads();

    int q = lane >> 2;
    int r = lane & 3;
    float c[8][4];
#pragma unroll
    for (int n = 0; n < 8; ++n)
#pragma unroll
        for (int t = 0; t < 4; ++t) c[n][t] = 0.f;

    int arow = warp * 16;
#pragma unroll 4
    for (int kt = 0; kt < 16; ++kt) {
        int k0 = kt * 8;
        const float* Ab = As + (arow + q) * AS_STRIDE + k0 + r;
        unsigned int a0 = __float_as_uint(Ab[0]);
        unsigned int a1 = __float_as_uint(Ab[8 * AS_STRIDE]);
        unsigned int a2 = __float_as_uint(Ab[4]);
        unsigned int a3 = __float_as_uint(Ab[8 * AS_STRIDE + 4]);
#pragma unroll
        for (int n = 0; n < 8; ++n) {
            const float* Bb = Bs + (k0 + r) * BS_STRIDE + n * 8 + q;
            unsigned int b0 = __float_as_uint(Bb[0]);
            unsigned int b1 = __float_as_uint(Bb[4 * BS_STRIDE]);
            mma_tf32(c[n], a0, a1, a2, a3, b0, b1);
        }
    }

    int gr0 = row0 + arow + q;
    int gr1 = gr0 + 8;
#pragma unroll
    for (int n = 0; n < 8; ++n) {
        int j = n * 8 + 2 * r;
        float x0 = c[n][0], x1 = c[n][1], x2 = c[n][2], x3 = c[n][3];
        if (BN_RELU) {
            float sc0 = s_scale[j], sh0 = s_shift[j];
            float sc1 = s_scale[j + 1], sh1 = s_shift[j + 1];
            x0 = fmaxf(fmaf(x0, sc0, sh0), 0.f);
            x1 = fmaxf(fmaf(x1, sc1, sh1), 0.f);
            x2 = fmaxf(fmaf(x2, sc0, sh0), 0.f);
            x3 = fmaxf(fmaf(x3, sc1, sh1), 0.f);
        }
        if (gr0 < nNodes)
            *(float2*)(out + (size_t)gr0 * F + j) = make_float2(x0, x1);
        if (gr1 < nNodes)
            *(float2*)(out + (size_t)gr1 * F + j) = make_float2(x2, x3);
    }
}

// ---------------------------------------------------------------------------
__global__ void colsum_kernel(const float* __restrict__ hin, int nNodes) {
    int t = blockIdx.x * blockDim.x + threadIdx.x;
    int col = t & 63;
    int r = t >> 6;
    int stride = (gridDim.x * blockDim.x) >> 6;
    float s = 0.f;
    for (; r < nNodes; r += stride) s += __ldg(&hin[(size_t)r * F + col]);
    atomicAdd(&g_colsum[col], s);
}

__global__ void head_kernel(const float* __restrict__ bl2,
                            const float* __restrict__ cw1,
                            const float* __restrict__ cb1,
                            const float* __restrict__ cw2,
                            const float* __restrict__ cb2,
                            float* __restrict__ outp, int nNodes) {
    __shared__ float mean[F];
    __shared__ float z[F];
    int t = threadIdx.x;
    mean[t] = g_colsum[t] / (float)nNodes + __ldg(&bl2[t]);
    __syncthreads();
    float s = __ldg(&cb1[t]);
#pragma unroll
    for (int j = 0; j < F; ++j) s = fmaf(mean[j], __ldg(&cw1[t * F + j]), s);
    z[t] = fmaxf(s, 0.f);
    __syncthreads();
    if (t == 0) {
        float o = __ldg(&cb2[0]);
#pragma unroll
        for (int i = 0; i < F; ++i) o = fmaf(z[i], __ldg(&cw2[i]), o);
        outp[0] = 1.f / (1.f + expf(-o));
    }
}

// ---------------------------------------------------------------------------
extern "C" void kernel_launch(void* const* d_in, const int* in_sizes, int n_in,
                              void* d_out, int out_size) {
    const float* x    = (const float*)d_in[0];
    const int*   eidx = (const int*)d_in[1];
    const float* w_l0 = (const float*)d_in[2];
    const float* b_l0 = (const float*)d_in[3];
    const float* w_r0 = (const float*)d_in[4];
    const float* w_l1 = (const float*)d_in[5];
    const float* b_l1 = (const float*)d_in[6];
    const float* w_r1 = (const float*)d_in[7];
    const float* w_l2 = (const float*)d_in[8];
    const float* b_l2 = (const float*)d_in[9];
    const float* w_r2 = (const float*)d_in[10];
    const float* g0   = (const float*)d_in[11];
    const float* be0  = (const float*)d_in[12];
    const float* m0   = (const float*)d_in[13];
    const float* v0   = (const float*)d_in[14];
    const float* g1   = (const float*)d_in[15];
    const float* be1  = (const float*)d_in[16];
    const float* m1   = (const float*)d_in[17];
    const float* v1   = (const float*)d_in[18];
    const float* cw1  = (const float*)d_in[19];
    const float* cb1  = (const float*)d_in[20];
    const float* cw2  = (const float*)d_in[21];
    const float* cb2  = (const float*)d_in[22];
    float* out = (float*)d_out;

    int nN = in_sizes[0] / F;
    int E = in_sizes[1] / 2;
    if (nN > MAXN) nN = MAXN;
    if (E > MAXE) E = MAXE;
    const int* srcp = eidx;
    const int* dstp = eidx + E;

    float *bufA, *bufB;
    int* degp;
    float* colsump;
    cudaGetSymbolAddress((void**)&bufA, g_bufA);
    cudaGetSymbolAddress((void**)&bufB, g_bufB);
    cudaGetSymbolAddress((void**)&degp, g_deg);
    cudaGetSymbolAddress((void**)&colsump, g_colsum);

    cudaFuncSetAttribute(gemm_mma_kernel<true>,
                         cudaFuncAttributeMaxDynamicSharedMemorySize,
                         GEMM_SMEM_BYTES);
    cudaFuncSetAttribute(gemm_mma_kernel<false>,
                         cudaFuncAttributeMaxDynamicSharedMemorySize,
                         GEMM_SMEM_BYTES);

    int tb = 256;
    cudaMemsetAsync(degp, 0, (size_t)nN * sizeof(int));
    cudaMemsetAsync(colsump, 0, F * sizeof(float));
    hist_kernel<<<(E + tb - 1) / tb, tb>>>(dstp, E);
    scan_pass1<<<256, 256>>>(nN);
    scan_pass3<<<256, 256>>>(nN);
    scatter_kernel<<<(E + tb - 1) / tb, tb>>>(srcp, dstp, E);

    int aggBlocks = (nN + 7) / 8;
    int gemmBlocks = (nN + 63) / 64;

    // Layer 0: x -> bufA
    aggregate_kernel<<<aggBlocks, tb>>>(x, nN);
    gemm_mma_kernel<true><<<gemmBlocks, 128, GEMM_SMEM_BYTES>>>(
        x, w_l0, w_r0, b_l0, g0, be0, m0, v0, bufA, nN);
    // Layer 1: bufA -> bufB
    aggregate_kernel<<<aggBlocks, tb>>>(bufA, nN);
    gemm_mma_kernel<true><<<gemmBlocks, 128, GEMM_SMEM_BYTES>>>(
        bufA, w_l1, w_r1, b_l1, g1, be1, m1, v1, bufB, nN);
    // Layer 2: bufB -> bufA (no BN/ReLU, bias deferred)
    aggregate_kernel<<<aggBlocks, tb>>>(bufB, nN);
    gemm_mma_kernel<false><<<gemmBlocks, 128, GEMM_SMEM_BYTES>>>(
        bufB, w_l2, w_r2, b_l2, nullptr, nullptr, nullptr, nullptr, bufA, nN);

    colsum_kernel<<<256, tb>>>(bufA, nN);
    head_kernel<<<1, F>>>(b_l2, cw1, cb1, cw2, cb2, out, nN);
}